// round 9
// baseline (speedup 1.0000x reference)
#include <cuda_runtime.h>

#define B  32
#define L  1024
#define D  512
#define NN 512

// 8 partial-sum planes of sum_l(i - j) over L-eighths: [8][B][D]
__device__ float g_part[8 * B * D];
// transposed mean-diff: g_mdT[d][b]  (64 KB, L2-hot)
__device__ float g_mdT[D * B];
// 16 partial GEMV planes: g_up[dc][b][n]  (1 MB, L2-hot)
__device__ float g_up[16 * B * NN];
// DCE-defeating sink for the W prefetch
__device__ float g_sink;

// ---------------------------------------------------------------------------
// Kernel 1 (unchanged): part[lo][b][d] = sum_{l in eighth} (i - j)
// 1024 blocks x 256 thr, all resident. Full-warp 512B LDG.128 rows, __ldcs.
// Side job: prefetch W (1 MB) into L2.
// ---------------------------------------------------------------------------
__global__ void __launch_bounds__(256, 8) mean_diff_kernel(
    const float* __restrict__ gi, const float* __restrict__ gj,
    const float* __restrict__ W)
{
    const int blk = blockIdx.x;
    const int b   = blk >> 5;
    const int r   = blk & 31;
    const int dt  = r >> 3;           // 128-float d tile (4 per D)
    const int lo  = r & 7;            // L eighth
    const int tid = threadIdx.x;
    const int dq  = tid & 31;
    const int lg  = tid >> 5;

    if (tid < 64) {
        float4 w = __ldcg(((const float4*)W) + blk * 64 + tid);
        float t = w.x + w.y + w.z + w.w;
        if (__float_as_int(t) == 0x7f800001)  // never true in practice
            g_sink = t;
    }

    const int rowq = D / 4;
    const float4* pi = (const float4*)(gi + (size_t)b * L * D) + dt * 32 + dq;
    const float4* pj = (const float4*)(gj + (size_t)b * L * D) + dt * 32 + dq;

    const int l0 = lo * 128 + lg * 16;
    float4 acc = make_float4(0.f, 0.f, 0.f, 0.f);
    #pragma unroll
    for (int rr = 0; rr < 16; rr++) {
        size_t off = (size_t)(l0 + rr) * rowq;
        float4 a = __ldcs(pi + off);
        float4 c = __ldcs(pj + off);
        acc.x += a.x - c.x;
        acc.y += a.y - c.y;
        acc.z += a.z - c.z;
        acc.w += a.w - c.w;
    }

    __shared__ float4 s[256];
    s[tid] = acc;
    __syncthreads();

    #pragma unroll
    for (int stride = 128; stride >= 32; stride >>= 1) {
        if (tid < stride) {
            float4 o = s[tid + stride];
            s[tid].x += o.x; s[tid].y += o.y; s[tid].z += o.z; s[tid].w += o.w;
        }
        __syncthreads();
    }

    if (tid < 32)
        ((float4*)(g_part + lo * B * D + b * D + dt * 128))[tid] = s[tid];
}

// ---------------------------------------------------------------------------
// Kernel 2: g_mdT[d][b] = (1/L) * sum_pl g_part[pl][b][d]
// 64 blocks x 256 thr; coalesced plane reads, scattered (cheap) stores.
// ---------------------------------------------------------------------------
__global__ void __launch_bounds__(256) reduce_md_kernel()
{
    const int t = blockIdx.x * 256 + threadIdx.x;   // t = b*D + d
    const int b = t >> 9;
    const int d = t & 511;

    float v = 0.f;
    #pragma unroll
    for (int pl = 0; pl < 8; pl++)
        v += g_part[pl * B * D + t];

    g_mdT[d * B + b] = v * (1.0f / (float)L);
}

// ---------------------------------------------------------------------------
// Kernel 3: partial GEMV with FULL 32-batch reuse of W.
// Grid: 16 d-chunks x 16 n-chunks = 256 blocks x 256 thr.
// Per block: stage W[32d][32n] (4KB) + mdT[32d][32b] (4KB) in smem, then
// each thread (n = tid&31, bg = tid>>5) accumulates 4 batches over 32 d:
//   per d: 1 conflict-free LDS row (sW) + 1 float4 broadcast LDS (smd) + 4 FMA.
// Writes g_up[dc][b][n]. Total W L2 traffic: 1 MB (was 16 MB).
// ---------------------------------------------------------------------------
__global__ void __launch_bounds__(256) gemv_partial_kernel(
    const float* __restrict__ W)
{
    const int blk = blockIdx.x;
    const int dc  = blk >> 4;        // d-chunk (32 rows)
    const int nc  = blk & 15;        // n-chunk (32 cols)
    const int tid = threadIdx.x;

    __shared__ float sW[32][32];     // [d][n]
    __shared__ float smd[32][32];    // [d][b]

    #pragma unroll
    for (int k = 0; k < 4; k++) {
        int e = k * 256 + tid;
        int dd = e >> 5;
        int c  = e & 31;
        sW[dd][c]  = W[(size_t)(dc * 32 + dd) * NN + nc * 32 + c];
        smd[dd][c] = g_mdT[(dc * 32 + dd) * B + c];
    }
    __syncthreads();

    const int n  = tid & 31;
    const int bg = tid >> 5;         // 8 groups x 4 batches

    float4 u = make_float4(0.f, 0.f, 0.f, 0.f);
    #pragma unroll
    for (int d = 0; d < 32; d++) {
        float  w = sW[d][n];
        float4 m = *(const float4*)&smd[d][bg * 4];
        u.x = fmaf(m.x, w, u.x);
        u.y = fmaf(m.y, w, u.y);
        u.z = fmaf(m.z, w, u.z);
        u.w = fmaf(m.w, w, u.w);
    }

    float* up = g_up + dc * B * NN + (bg * 4) * NN + nc * 32 + n;
    up[0]      = u.x;
    up[NN]     = u.y;
    up[2 * NN] = u.z;
    up[3 * NN] = u.w;
}

// ---------------------------------------------------------------------------
// Kernel 4: out[b][n] = 0.5*(relu(u+bias) + relu(bias-u)),
//           u = sum over 16 d-chunk partials. 64 blocks x 256 thr.
// ---------------------------------------------------------------------------
__global__ void __launch_bounds__(256) combine_kernel(
    const float* __restrict__ bias, float* __restrict__ out)
{
    const int t = blockIdx.x * 256 + threadIdx.x;   // t = b*NN + n
    const int n = t & (NN - 1);

    float u = 0.f;
    #pragma unroll
    for (int dcc = 0; dcc < 16; dcc++)
        u += g_up[dcc * B * NN + t];

    float bv = bias[n];
    out[t] = 0.5f * (fmaxf(u + bv, 0.f) + fmaxf(bv - u, 0.f));
}

extern "C" void kernel_launch(void* const* d_in, const int* in_sizes, int n_in,
                              void* d_out, int out_size)
{
    const float* gi   = (const float*)d_in[0];   // i     [B, L, D]
    const float* gj   = (const float*)d_in[1];   // j     [B, L, D]
    const float* W    = (const float*)d_in[2];   // W_agg [D, NN]
    const float* bias = (const float*)d_in[3];   // b_agg [NN]
    float* out = (float*)d_out;                  // [B, NN]

    mean_diff_kernel<<<1024, 256>>>(gi, gj, W);
    reduce_md_kernel<<<64, 256>>>();
    gemv_partial_kernel<<<256, 256>>>(W);
    combine_kernel<<<64, 256>>>(bias, out);
}

// round 10
// speedup vs baseline: 1.0662x; 1.0662x over previous
#include <cuda_runtime.h>

#define B  32
#define L  1024
#define D  512
#define NN 512

// 8 partial-sum planes of sum_l(i - j) over L-eighths: [8][B][D]
__device__ float g_part[8 * B * D];
// DCE-defeating sink for the W prefetch
__device__ float g_sink;

// ---------------------------------------------------------------------------
// Kernel 1 (unchanged — measured ~22.9us, ~5.6 TB/s):
// part[lo][b][d] = sum_{l in eighth lo} (i[b,l,d] - j[b,l,d])
// 1024 blocks x 256 thr, all resident (8 blocks/SM, <=32 regs).
// Full-warp 512B LDG.128 rows, __ldcs streaming so W stays in L2.
// Side job: prefetch W (1 MB) into L2 for kernel 2.
// ---------------------------------------------------------------------------
__global__ void __launch_bounds__(256, 8) mean_diff_kernel(
    const float* __restrict__ gi, const float* __restrict__ gj,
    const float* __restrict__ W)
{
    const int blk = blockIdx.x;
    const int b   = blk >> 5;         // batch
    const int r   = blk & 31;
    const int dt  = r >> 3;           // 128-float d tile (4 per D)
    const int lo  = r & 7;            // L eighth
    const int tid = threadIdx.x;
    const int dq  = tid & 31;         // float4 within 128-float tile
    const int lg  = tid >> 5;         // l-group (8 groups x 16 rows)

    // --- W prefetch: 1024 blocks x 64 float4 = 1 MB into L2 ---
    if (tid < 64) {
        float4 w = __ldcg(((const float4*)W) + blk * 64 + tid);
        float t = w.x + w.y + w.z + w.w;
        if (__float_as_int(t) == 0x7f800001)  // never true in practice
            g_sink = t;
    }

    const int rowq = D / 4;           // 128 float4 per row
    const float4* pi = (const float4*)(gi + (size_t)b * L * D) + dt * 32 + dq;
    const float4* pj = (const float4*)(gj + (size_t)b * L * D) + dt * 32 + dq;

    const int l0 = lo * 128 + lg * 16;
    float4 acc = make_float4(0.f, 0.f, 0.f, 0.f);
    #pragma unroll
    for (int rr = 0; rr < 16; rr++) {
        size_t off = (size_t)(l0 + rr) * rowq;
        float4 a = __ldcs(pi + off);
        float4 c = __ldcs(pj + off);
        acc.x += a.x - c.x;
        acc.y += a.y - c.y;
        acc.z += a.z - c.z;
        acc.w += a.w - c.w;
    }

    __shared__ float4 s[256];
    s[tid] = acc;
    __syncthreads();

    #pragma unroll
    for (int stride = 128; stride >= 32; stride >>= 1) {
        if (tid < stride) {
            float4 o = s[tid + stride];
            s[tid].x += o.x; s[tid].y += o.y; s[tid].z += o.z; s[tid].w += o.w;
        }
        __syncthreads();
    }

    if (tid < 32)
        ((float4*)(g_part + lo * B * D + b * D + dt * 128))[tid] = s[tid];
}

// ---------------------------------------------------------------------------
// Kernel 2: md[b,d] = (1/L) * sum_lo part[lo][b][d]
//           u[b,n]  = sum_d md[b,d] * W[d,n]
//           out[b,n] = 0.5*(relu(u + bias[n]) + relu(bias[n] - u))
// Grid: 16 batch-pairs * 32 n-tiles(16 wide) = 512 blocks x 512 threads
// (2x R6's thread-level parallelism at the SAME 16 MB W L2 traffic).
// Thread map: nloc = tid&15, dg = tid>>4 (32 d-groups of 16 rows).
// Per thread: 16 fully-unrolled independent W loads (all in flight),
// each reused for 2 batches.
// ---------------------------------------------------------------------------
__global__ void __launch_bounds__(512) gemv_combine_kernel(
    const float* __restrict__ W, const float* __restrict__ bias,
    float* __restrict__ out)
{
    const int blk  = blockIdx.x;
    const int bg   = blk >> 5;        // batch pair (2 batches)
    const int nt   = blk & 31;        // 16-wide n tile
    const int b0   = bg * 2;
    const int tid  = threadIdx.x;
    const int nloc = tid & 15;
    const int dg   = tid >> 4;        // d-group 0..31 (16 rows each)

    __shared__ float smd[2][D];
    {
        const float inv = 1.0f / (float)L;
        #pragma unroll
        for (int bb = 0; bb < 2; bb++) {
            const float* p = g_part + (b0 + bb) * D + tid;
            float v = 0.f;
            #pragma unroll
            for (int pl = 0; pl < 8; pl++)
                v += p[pl * B * D];
            smd[bb][tid] = v * inv;
        }
    }
    __syncthreads();

    const int n = nt * 16 + nloc;
    const float* Wp = W + (size_t)(dg * 16) * NN + n;

    float u0 = 0.f, u1 = 0.f;
    #pragma unroll
    for (int d = 0; d < 16; d++) {
        float w = __ldg(Wp + (size_t)d * NN);
        int di = dg * 16 + d;
        u0 = fmaf(smd[0][di], w, u0);
        u1 = fmaf(smd[1][di], w, u1);
    }

    __shared__ float su[2][512];
    su[0][tid] = u0;
    su[1][tid] = u1;
    __syncthreads();

    // 32 results (2 batches x 16 n), each a 32-way partial sum.
    if (tid < 32) {
        const int bb = tid >> 4;      // batch within pair
        const int nn = tid & 15;
        float t = 0.f;
        #pragma unroll
        for (int g = 0; g < 32; g++)
            t += su[bb][g * 16 + nn];
        float bv = bias[nt * 16 + nn];
        out[(b0 + bb) * NN + nt * 16 + nn] =
            0.5f * (fmaxf(t + bv, 0.f) + fmaxf(bv - t, 0.f));
    }
}

extern "C" void kernel_launch(void* const* d_in, const int* in_sizes, int n_in,
                              void* d_out, int out_size)
{
    const float* gi   = (const float*)d_in[0];   // i     [B, L, D]
    const float* gj   = (const float*)d_in[1];   // j     [B, L, D]
    const float* W    = (const float*)d_in[2];   // W_agg [D, NN]
    const float* bias = (const float*)d_in[3];   // b_agg [NN]
    float* out = (float*)d_out;                  // [B, NN]

    mean_diff_kernel<<<1024, 256>>>(gi, gj, W);
    gemv_combine_kernel<<<512, 512>>>(W, bias, out);
}

// round 11
// speedup vs baseline: 1.0816x; 1.0145x over previous
#include <cuda_runtime.h>

#define B  32
#define L  1024
#define D  512
#define NN 512

// 8 partial-sum planes of sum_l(i - j) over L-eighths: [8][B][D]
__device__ float g_part[8 * B * D];
// DCE-defeating sink for the W prefetch
__device__ float g_sink;

// ---------------------------------------------------------------------------
// Kernel 1 (unchanged — measured ~22.9us, ~5.6 TB/s):
// part[lo][b][d] = sum_{l in eighth lo} (i[b,l,d] - j[b,l,d])
// 1024 blocks x 256 thr, all resident (8 blocks/SM, <=32 regs).
// Full-warp 512B LDG.128 rows, __ldcs streaming so W stays in L2.
// Side job: prefetch W (1 MB) into L2 for kernel 2.
// ---------------------------------------------------------------------------
__global__ void __launch_bounds__(256, 8) mean_diff_kernel(
    const float* __restrict__ gi, const float* __restrict__ gj,
    const float* __restrict__ W)
{
    const int blk = blockIdx.x;
    const int b   = blk >> 5;         // batch
    const int r   = blk & 31;
    const int dt  = r >> 3;           // 128-float d tile (4 per D)
    const int lo  = r & 7;            // L eighth
    const int tid = threadIdx.x;
    const int dq  = tid & 31;         // float4 within 128-float tile
    const int lg  = tid >> 5;         // l-group (8 groups x 16 rows)

    // --- W prefetch: 1024 blocks x 64 float4 = 1 MB into L2 ---
    if (tid < 64) {
        float4 w = __ldcg(((const float4*)W) + blk * 64 + tid);
        float t = w.x + w.y + w.z + w.w;
        if (__float_as_int(t) == 0x7f800001)  // never true in practice
            g_sink = t;
    }

    const int rowq = D / 4;           // 128 float4 per row
    const float4* pi = (const float4*)(gi + (size_t)b * L * D) + dt * 32 + dq;
    const float4* pj = (const float4*)(gj + (size_t)b * L * D) + dt * 32 + dq;

    const int l0 = lo * 128 + lg * 16;
    float4 acc = make_float4(0.f, 0.f, 0.f, 0.f);
    #pragma unroll
    for (int rr = 0; rr < 16; rr++) {
        size_t off = (size_t)(l0 + rr) * rowq;
        float4 a = __ldcs(pi + off);
        float4 c = __ldcs(pj + off);
        acc.x += a.x - c.x;
        acc.y += a.y - c.y;
        acc.z += a.z - c.z;
        acc.w += a.w - c.w;
    }

    __shared__ float4 s[256];
    s[tid] = acc;
    __syncthreads();

    #pragma unroll
    for (int stride = 128; stride >= 32; stride >>= 1) {
        if (tid < stride) {
            float4 o = s[tid + stride];
            s[tid].x += o.x; s[tid].y += o.y; s[tid].z += o.z; s[tid].w += o.w;
        }
        __syncthreads();
    }

    if (tid < 32)
        ((float4*)(g_part + lo * B * D + b * D + dt * 128))[tid] = s[tid];
}

// ---------------------------------------------------------------------------
// Kernel 2: md[b,d] = (1/L) * sum_lo part[lo][b][d]
//           u[b,n]  = sum_d md[b,d] * W[d,n]
//           out[b,n] = 0.5*(relu(u + bias[n]) + relu(bias[n] - u))
// Grid: 32 batches * 4 n-tiles(128 floats) = 128 blocks (ONE wave, <=148)
// x 512 threads. Thread map: q = tid&31 (float4 col -> warp reads a full
// 512B W row segment), dg = tid>>5 (16 d-groups of 32 rows).
// Per thread: 32 independent float4 W loads + 128 FMAs. All W hits L2
// (prefetched by kernel 1).
// ---------------------------------------------------------------------------
__global__ void __launch_bounds__(512) gemv_combine_kernel(
    const float* __restrict__ W, const float* __restrict__ bias,
    float* __restrict__ out)
{
    const int blk = blockIdx.x;
    const int b   = blk >> 2;         // batch
    const int nt  = blk & 3;          // 128-float n tile
    const int tid = threadIdx.x;
    const int q   = tid & 31;         // float4 column within tile
    const int dg  = tid >> 5;         // d-group 0..15 (32 rows each)

    // plane-reduce: md[b, tid] for all 512 d
    __shared__ float smd[D];
    {
        const float inv = 1.0f / (float)L;
        const float* p = g_part + b * D + tid;
        float v = 0.f;
        #pragma unroll
        for (int pl = 0; pl < 8; pl++)
            v += p[pl * B * D];
        smd[tid] = v * inv;
    }
    __syncthreads();

    // W as float4: row d occupies 128 float4; this block's tile starts at
    // column nt*32 (in float4 units).
    const float4* W4 = (const float4*)W + (size_t)(dg * 32) * (NN / 4) + nt * 32 + q;

    float4 u = make_float4(0.f, 0.f, 0.f, 0.f);
    #pragma unroll
    for (int d = 0; d < 32; d++) {
        float4 w = __ldg(W4 + (size_t)d * (NN / 4));
        float  m = smd[dg * 32 + d];
        u.x = fmaf(m, w.x, u.x);
        u.y = fmaf(m, w.y, u.y);
        u.z = fmaf(m, w.z, u.z);
        u.w = fmaf(m, w.w, u.w);
    }

    __shared__ float4 su[512];
    su[tid] = u;
    __syncthreads();

    // reduce over the 16 d-groups (stride 32 in tid space)
    #pragma unroll
    for (int stride = 256; stride >= 32; stride >>= 1) {
        if (tid < stride) {
            float4 o = su[tid + stride];
            su[tid].x += o.x; su[tid].y += o.y; su[tid].z += o.z; su[tid].w += o.w;
        }
        __syncthreads();
    }

    if (tid < 32) {
        float4 t  = su[tid];
        float4 bv = ((const float4*)bias)[nt * 32 + tid];
        float4 r;
        r.x = 0.5f * (fmaxf(t.x + bv.x, 0.f) + fmaxf(bv.x - t.x, 0.f));
        r.y = 0.5f * (fmaxf(t.y + bv.y, 0.f) + fmaxf(bv.y - t.y, 0.f));
        r.z = 0.5f * (fmaxf(t.z + bv.z, 0.f) + fmaxf(bv.z - t.z, 0.f));
        r.w = 0.5f * (fmaxf(t.w + bv.w, 0.f) + fmaxf(bv.w - t.w, 0.f));
        ((float4*)out)[b * (NN / 4) + nt * 32 + tid] = r;
    }
}

extern "C" void kernel_launch(void* const* d_in, const int* in_sizes, int n_in,
                              void* d_out, int out_size)
{
    const float* gi   = (const float*)d_in[0];   // i     [B, L, D]
    const float* gj   = (const float*)d_in[1];   // j     [B, L, D]
    const float* W    = (const float*)d_in[2];   // W_agg [D, NN]
    const float* bias = (const float*)d_in[3];   // b_agg [NN]
    float* out = (float*)d_out;                  // [B, NN]

    mean_diff_kernel<<<1024, 256>>>(gi, gj, W);
    gemv_combine_kernel<<<128, 512>>>(W, bias, out);
}